// round 14
// baseline (speedup 1.0000x reference)
#include <cuda_runtime.h>
#include <cuda_fp16.h>
#include <math.h>
#include <stdint.h>

// ---------------- problem constants ----------------
#define NTOK  2048
#define HID   1024
#define ITR   2816
#define NEXP  8
#define NADP  2
#define RNK   16
#define TOPK  2
#define NSEQ  8
#define NPAIR (NTOK*TOPK)        // 4096
#define NPAD  (NPAIR + 128)

// ---------------- GEMM tiling (mma.sync m16n8k16 fp16) ----------------
#define BM 128
#define BN 128
#define STAGEB 32768              // A tile 16KB + B tile 16KB
#define NSTG 3
#define SMEM_DYN (NSTG*STAGEB)    // 98304
#define NK1 17                    // 16 real + 1 lora-ext
#define NK2 45                    // 44 real + 1 lora-ext
#define MAXT (NPAIR/BM + NEXP)    // 40
#define NCT1 (ITR/64)             // 44
#define NCT2 (HID/BN)             // 8
// lora-A GEMM (N=64)
#define LSTAGE 24576              // A 16KB + B 8KB
#define LSMEM (NSTG*LSTAGE)       // 73728

// ---------------- device scratch ----------------
__device__ int   g_tok[NPAIR];
__device__ float g_w[NPAIR];
__device__ int   g_ad[NPAIR];
__device__ float g_scale[NPAIR];
__device__ int   g2_ntiles;
__device__ int   g2_e[MAXT];
__device__ int   g2_m0[MAXT];
__device__ int   g2_rows[MAXT];
__device__ __align__(16) __half g_xg_h[(size_t)NPAD*HID];
__device__ __align__(16) __half g_act_h[(size_t)NPAD*ITR];
__device__ __align__(16) __half g_zgu_h[(size_t)NPAD*64];
__device__ __align__(16) __half g_zd_h[(size_t)NPAD*64];
__device__ float g_zd_f[(size_t)NPAIR*32];
__device__ __align__(16) __half g_wgu_h[(size_t)NEXP*2*ITR*HID];
__device__ __align__(16) __half g_wd_h[(size_t)NEXP*HID*ITR];
__device__ __align__(16) __half g_bg_ext[(size_t)NEXP*2*ITR*64];
__device__ __align__(16) __half g_bd_ext[(size_t)NEXP*HID*64];
__device__ __align__(16) __half g_a1h[(size_t)NEXP*64*HID];   // [e][ga0|ua0|ga1|ua1][HID]
__device__ __align__(16) __half g_a2h[(size_t)NEXP*64*ITR];   // [e][da0|da1|zeros][ITR]

// ---------------- PTX helpers ----------------
__device__ __forceinline__ uint32_t s2u(const void* p){
    uint32_t a;
    asm("{ .reg .u64 t; cvta.to.shared.u64 t, %1; cvt.u32.u64 %0, t; }":"=r"(a):"l"(p));
    return a;
}
__device__ __forceinline__ void cpa16(uint32_t dst, const void* src){
    asm volatile("cp.async.cg.shared.global [%0], [%1], 16;" :: "r"(dst), "l"(src));
}
__device__ __forceinline__ void cp_commit(){ asm volatile("cp.async.commit_group;":::"memory"); }
__device__ __forceinline__ void cp_wait1(){ asm volatile("cp.async.wait_group 1;":::"memory"); }
__device__ __forceinline__ void cp_wait0(){ asm volatile("cp.async.wait_group 0;":::"memory"); }
__device__ __forceinline__ void ldsm4(uint32_t* r, uint32_t addr){
    asm volatile("ldmatrix.sync.aligned.m8n8.x4.shared.b16 {%0,%1,%2,%3}, [%4];"
      : "=r"(r[0]),"=r"(r[1]),"=r"(r[2]),"=r"(r[3]) : "r"(addr));
}
__device__ __forceinline__ void mma16(float* c, const uint32_t* a, const uint32_t* b){
    asm volatile("mma.sync.aligned.m16n8k16.row.col.f32.f16.f16.f32 "
      "{%0,%1,%2,%3},{%4,%5,%6,%7},{%8,%9},{%0,%1,%2,%3};"
      : "+f"(c[0]),"+f"(c[1]),"+f"(c[2]),"+f"(c[3])
      : "r"(a[0]),"r"(a[1]),"r"(a[2]),"r"(a[3]),"r"(b[0]),"r"(b[1]));
}

// ---------------- BN=128 mainloop compute ----------------
__device__ __forceinline__ void stage_mma(uint32_t smA, uint32_t smB,
                                          int lane, int wm, int wn,
                                          float (*acc)[4][4])
{
    int ra = (lane & 7) + (((lane >> 3) & 1) << 3);
    int ka = lane >> 4;
    int rb = (lane & 7) + ((lane >> 4) << 3);
    int kb = (lane >> 3) & 1;
    #pragma unroll
    for (int ks = 0; ks < 4; ks++){
        uint32_t a[4][4], b[2][4];
        #pragma unroll
        for (int mf = 0; mf < 4; mf++){
            int row = wm*64 + mf*16 + ra;
            int kgr = ks*2 + ka;
            ldsm4(a[mf], smA + row*128 + ((kgr ^ (row & 7)) << 4));
        }
        #pragma unroll
        for (int nfp = 0; nfp < 2; nfp++){
            int row = wn*32 + nfp*16 + rb;
            int kgr = ks*2 + kb;
            ldsm4(b[nfp], smB + row*128 + ((kgr ^ (row & 7)) << 4));
        }
        #pragma unroll
        for (int mf = 0; mf < 4; mf++){
            mma16(acc[mf][0], a[mf], b[0] + 0);
            mma16(acc[mf][1], a[mf], b[0] + 2);
            mma16(acc[mf][2], a[mf], b[1] + 0);
            mma16(acc[mf][3], a[mf], b[1] + 2);
        }
    }
}

// ---------------- BN=64 mainloop compute (lora-A GEMM) ----------------
__device__ __forceinline__ void stage_mma64(uint32_t smA, uint32_t smB,
                                            int lane, int wm, int wn,
                                            float (*acc)[4][4])   // acc[2][4][4]
{
    int ra = (lane & 7) + (((lane >> 3) & 1) << 3);
    int ka = lane >> 4;
    int rb = (lane & 7) + ((lane >> 4) << 3);
    int kb = (lane >> 3) & 1;
    #pragma unroll
    for (int ks = 0; ks < 4; ks++){
        uint32_t a[2][4], b[2][4];
        #pragma unroll
        for (int mf = 0; mf < 2; mf++){
            int row = wm*32 + mf*16 + ra;
            int kgr = ks*2 + ka;
            ldsm4(a[mf], smA + row*128 + ((kgr ^ (row & 7)) << 4));
        }
        #pragma unroll
        for (int nfp = 0; nfp < 2; nfp++){
            int row = wn*32 + nfp*16 + rb;
            int kgr = ks*2 + kb;
            ldsm4(b[nfp], smB + row*128 + ((kgr ^ (row & 7)) << 4));
        }
        #pragma unroll
        for (int mf = 0; mf < 2; mf++){
            mma16(acc[mf][0], a[mf], b[0] + 0);
            mma16(acc[mf][1], a[mf], b[0] + 2);
            mma16(acc[mf][2], a[mf], b[1] + 0);
            mma16(acc[mf][3], a[mf], b[1] + 2);
        }
    }
}

// ---------------- weight conversion kernels (side stream) ----------------
__global__ void k_convgu(const float* __restrict__ wgu)
{
    const size_t n1 = (size_t)NEXP*2*ITR*HID/4;
    size_t stride = (size_t)gridDim.x*blockDim.x;
    __half2* o1 = (__half2*)g_wgu_h;
    for (size_t i = (size_t)blockIdx.x*blockDim.x + threadIdx.x; i < n1; i += stride){
        float4 v = ((const float4*)wgu)[i];
        o1[2*i]   = __float22half2_rn(make_float2(v.x, v.y));
        o1[2*i+1] = __float22half2_rn(make_float2(v.z, v.w));
    }
}
__global__ void k_convwd(const float* __restrict__ wd)
{
    const size_t n2 = (size_t)NEXP*HID*ITR/4;
    size_t stride = (size_t)gridDim.x*blockDim.x;
    __half2* o2 = (__half2*)g_wd_h;
    for (size_t i = (size_t)blockIdx.x*blockDim.x + threadIdx.x; i < n2; i += stride){
        float4 v = ((const float4*)wd)[i];
        o2[2*i]   = __float22half2_rn(make_float2(v.x, v.y));
        o2[2*i+1] = __float22half2_rn(make_float2(v.z, v.w));
    }
}

// ---------------- setup ----------------
__global__ void k_setup(const int* __restrict__ topk_ids, const float* __restrict__ topk_w,
                        const int* __restrict__ widx, const int* __restrict__ seq_lens,
                        const float* __restrict__ scalings)
{
    __shared__ int cnt[NEXP*NADP], off[NEXP*NADP], cur[NEXP*NADP], cum[NSEQ];
    int tid = threadIdx.x;
    if (tid < NEXP*NADP) cnt[tid] = 0;
    __syncthreads();
    if (tid == 0){ int c = 0; for (int s = 0; s < NSEQ; s++){ c += seq_lens[s]; cum[s] = c; } }
    __syncthreads();
    for (int p = tid; p < NPAIR; p += blockDim.x){
        int n = p / TOPK; int e = topk_ids[p];
        int s = 0; while (n >= cum[s]) s++;
        atomicAdd(&cnt[e*NADP + widx[s]], 1);
    }
    __syncthreads();
    if (tid == 0){
        int acc = 0;
        for (int k = 0; k < NEXP*NADP; k++){ off[k] = acc; cur[k] = acc; acc += cnt[k]; }
        int nt = 0;
        for (int e = 0; e < NEXP; e++){
            int base = off[e*NADP];
            int c = cnt[e*NADP] + cnt[e*NADP+1];
            for (int r0 = 0; r0 < c; r0 += BM){
                g2_e[nt] = e; g2_m0[nt] = base + r0; g2_rows[nt] = min(BM, c - r0); nt++;
            }
        }
        g2_ntiles = nt;
    }
    __syncthreads();
    for (int p = tid; p < NPAIR; p += blockDim.x){
        int n = p / TOPK; int e = topk_ids[p];
        int s = 0; while (n >= cum[s]) s++;
        int a = widx[s];
        int slot = atomicAdd(&cur[e*NADP + a], 1);
        g_tok[slot] = n; g_w[slot] = topk_w[p]; g_ad[slot] = a;
        g_scale[slot] = scalings[a];
    }
}

// ---------------- prep: lora tiles + gather + zero out + zero zd_f ----------------
__global__ void k_preall(const float* __restrict__ x,
                         const float* __restrict__ gate_a, const float* __restrict__ up_a,
                         const float* __restrict__ down_a,
                         const float* __restrict__ gb, const float* __restrict__ ub,
                         const float* __restrict__ db, const int* __restrict__ ranks,
                         float* __restrict__ out)
{
    size_t stride = (size_t)gridDim.x*blockDim.x;
    size_t tid0 = (size_t)blockIdx.x*blockDim.x + threadIdx.x;
    int r0 = ranks[0], r1 = ranks[1];
    {
        const size_t n = (size_t)NPAIR*(HID/4);
        for (size_t i = tid0; i < n; i += stride){
            int slot = (int)(i >> 8);
            int c = (int)(i & 255);
            float4 v = ((const float4*)(x + (size_t)g_tok[slot]*HID))[c];
            __half2* xh = (__half2*)(g_xg_h + (size_t)slot*HID);
            xh[2*c]   = __float22half2_rn(make_float2(v.x, v.y));
            xh[2*c+1] = __float22half2_rn(make_float2(v.z, v.w));
        }
    }
    {
        const size_t n = (size_t)NTOK*HID/4;
        for (size_t i = tid0; i < n; i += stride)
            ((float4*)out)[i] = make_float4(0.f, 0.f, 0.f, 0.f);
    }
    {
        const size_t n = (size_t)NPAIR*32/4;
        for (size_t i = tid0; i < n; i += stride)
            ((float4*)g_zd_f)[i] = make_float4(0.f, 0.f, 0.f, 0.f);
    }
    {
        const size_t n1 = (size_t)NEXP*2*ITR*64;
        for (size_t i = tid0; i < n1; i += stride){
            int c = (int)(i & 63);
            size_t R = (i >> 6);
            int e = (int)(R / (2*ITR));
            int r = (int)(R % (2*ITR));
            int j = r >> 1;
            float v = 0.f;
            if (!(r & 1)){
                if (c < 16) v = gb[((size_t)(0*NEXP + e)*ITR + j)*RNK + c];
                else if (c >= 32 && c < 48) v = gb[((size_t)(1*NEXP + e)*ITR + j)*RNK + (c - 32)];
            } else {
                if (c >= 16 && c < 32) v = ub[((size_t)(0*NEXP + e)*ITR + j)*RNK + (c - 16)];
                else if (c >= 48) v = ub[((size_t)(1*NEXP + e)*ITR + j)*RNK + (c - 48)];
            }
            g_bg_ext[i] = __float2half(v);
        }
    }
    {
        const size_t n2 = (size_t)NEXP*HID*64;
        for (size_t i = tid0; i < n2; i += stride){
            int c = (int)(i & 63);
            size_t R = (i >> 6);
            int e = (int)(R / HID);
            int h = (int)(R % HID);
            float v = 0.f;
            if (c < 16) v = db[((size_t)(0*NEXP + e)*HID + h)*RNK + c];
            else if (c < 32) v = db[((size_t)(1*NEXP + e)*HID + h)*RNK + (c - 16)];
            g_bd_ext[i] = __float2half(v);
        }
    }
    {
        const size_t n3 = (size_t)NEXP*64*HID;
        for (size_t i = tid0; i < n3; i += stride){
            int h = (int)(i & (HID-1));
            size_t R = i >> 10;
            int e = (int)(R >> 6);
            int r = (int)(R & 63);
            int aidx = r >> 5, within = r & 31, type = within >> 4, rr = within & 15;
            int rk = aidx ? r1 : r0;
            float v = 0.f;
            if (rr < rk){
                const float* src = (type == 0 ? gate_a : up_a)
                    + ((size_t)((aidx*NEXP + e)*RNK) + rr)*HID;
                v = src[h];
            }
            g_a1h[i] = __float2half(v);
        }
    }
    {
        const size_t n4 = (size_t)NEXP*64*ITR;
        for (size_t i = tid0; i < n4; i += stride){
            int h = (int)(i % ITR);
            size_t R = i / ITR;
            int e = (int)(R >> 6);
            int r = (int)(R & 63);
            float v = 0.f;
            if (r < 32){
                int aidx = r >> 4, rr = r & 15;
                int rk = aidx ? r1 : r0;
                if (rr < rk)
                    v = down_a[((size_t)((aidx*NEXP + e)*RNK) + rr)*ITR + h];
            }
            g_a2h[i] = __float2half(v);
        }
    }
}

// ---------------- lora-A GEMM fill ----------------
__device__ __forceinline__ void fillL(uint32_t smb, int s, int kc, int tid,
                                      const __half* Ab, int lda, const __half* Bb)
{
    uint32_t ab = smb + s*LSTAGE;
    uint32_t bb = ab + 16384;
    #pragma unroll
    for (int q = 0; q < 4; q++){
        int G = tid + 256*q; int row = G >> 3, gr = G & 7;
        cpa16(ab + row*128 + ((gr ^ (row & 7)) << 4), Ab + (size_t)row*lda + kc*64 + gr*8);
    }
    #pragma unroll
    for (int q = 0; q < 2; q++){
        int G = tid + 256*q; int row = G >> 3, gr = G & 7;
        cpa16(bb + row*128 + ((gr ^ (row & 7)) << 4), Bb + (size_t)row*lda + kc*64 + gr*8);
    }
}

// ---------------- lora-A GEMM for zgu ----------------
__global__ __launch_bounds__(256, 2) void k_loraA()
{
    int t = blockIdx.x;
    if (t >= g2_ntiles) return;
    int e = g2_e[t], m0 = g2_m0[t], rows = g2_rows[t];

    const __half* Ab = g_xg_h + (size_t)m0*HID;
    const __half* Bb = g_a1h + (size_t)e*64*HID;
    const int lda = HID, nk = 16;

    extern __shared__ char smc[];
    uint32_t smb = s2u(smc);
    int tid = threadIdx.x, lane = tid & 31, wid = tid >> 5;
    int wm = wid & 3, wn = wid >> 2;

    float acc[2][4][4];
    #pragma unroll
    for (int i = 0; i < 2; i++)
        #pragma unroll
        for (int j = 0; j < 4; j++)
            #pragma unroll
            for (int k = 0; k < 4; k++) acc[i][j][k] = 0.f;

    fillL(smb, 0, 0, tid, Ab, lda, Bb); cp_commit();
    fillL(smb, 1, 1, tid, Ab, lda, Bb); cp_commit();
    int sC = 0, sF = 2;
    for (int kc = 0; kc < nk; kc++){
        cp_wait1();
        __syncthreads();
        if (kc + 2 < nk){ fillL(smb, sF, kc + 2, tid, Ab, lda, Bb); }
        cp_commit();
        uint32_t st = smb + sC*LSTAGE;
        stage_mma64(st, st + 16384, lane, wm, wn, acc);
        sC = (sC == 2) ? 0 : sC + 1;
        sF = (sF == 2) ? 0 : sF + 1;
    }

    int g = lane >> 2, tg = lane & 3;
    #pragma unroll
    for (int mf = 0; mf < 2; mf++){
        #pragma unroll
        for (int h = 0; h < 2; h++){
            int row = wm*32 + mf*16 + g + h*8;
            if (row >= rows) continue;
            int slot = m0 + row;
            int a = g_ad[slot];
            float sc = g_scale[slot];
            __half* orow = g_zgu_h + (size_t)slot*64;
            #pragma unroll
            for (int nf = 0; nf < 4; nf++){
                #pragma unroll
                for (int p = 0; p < 2; p++){
                    int c = wn*32 + nf*8 + 2*tg + p;
                    float v = acc[mf][nf][h*2 + p];
                    bool keep = (a == 0) ? (c < 32) : (c >= 32);
                    orow[c] = __float2half(keep ? sc*v : 0.f);
                }
            }
        }
    }
}

// ---------------- GEMM1 fill ----------------
__device__ __forceinline__ void fill1(uint32_t smb, int s, int kc, int tid,
                                      int e, int m0, int j064)
{
    uint32_t ab = smb + s*STAGEB;
    uint32_t bb = ab + 16384;
    #pragma unroll
    for (int q = 0; q < 4; q++){
        int G = tid + 256*q; int row = G >> 3, gr = G & 7;
        uint32_t off = row*128 + ((gr ^ (row & 7)) << 4);
        const __half* sa = (kc < 16)
            ? g_xg_h + (size_t)(m0 + row)*HID + kc*64 + gr*8
            : g_zgu_h + (size_t)(m0 + row)*64 + gr*8;
        cpa16(ab + off, sa);
        const __half* sb;
        if (kc < 16){
            int sr = ((row & 1) ? ITR : 0) + j064 + (row >> 1);
            sb = g_wgu_h + ((size_t)e*(2*ITR) + sr)*HID + kc*64 + gr*8;
        } else {
            sb = g_bg_ext + ((size_t)e*(2*ITR) + 2*j064 + row)*64 + gr*8;
        }
        cpa16(bb + off, sb);
    }
}

// ---------------- GEMM1: gate/up + LoRA + SiLU -> act; zd partials ----------------
__global__ __launch_bounds__(256, 2) void k_gemm1()
{
    int t = blockIdx.x;
    if (t >= g2_ntiles) return;
    int e = g2_e[t], m0 = g2_m0[t], rows = g2_rows[t];
    int j064 = blockIdx.y * 64;

    extern __shared__ char smc[];
    uint32_t smb = s2u(smc);
    int tid = threadIdx.x, lane = tid & 31, wid = tid >> 5;
    int wm = wid & 1, wn = wid >> 1;

    float acc[4][4][4];
    #pragma unroll
    for (int i = 0; i < 4; i++)
        #pragma unroll
        for (int j = 0; j < 4; j++)
            #pragma unroll
            for (int k = 0; k < 4; k++) acc[i][j][k] = 0.f;

    fill1(smb, 0, 0, tid, e, m0, j064); cp_commit();
    fill1(smb, 1, 1, tid, e, m0, j064); cp_commit();
    int sC = 0, sF = 2;
    for (int kc = 0; kc < NK1; kc++){
        cp_wait1();
        __syncthreads();
        if (kc + 2 < NK1){ fill1(smb, sF, kc + 2, tid, e, m0, j064); }
        cp_commit();
        uint32_t st = smb + sC*STAGEB;
        stage_mma(st, st + 16384, lane, wm, wn, acc);
        sC = (sC == 2) ? 0 : sC + 1;
        sF = (sF == 2) ? 0 : sF + 1;
    }

    // fetch da tile for zd partial GEMM: rows 0..31 of g_a2h[e], K slice j064..j064+63
    {
        int row = tid >> 3, gr = tid & 7;  // 32 rows x 8 granules = 256
        cpa16(smb + 16384 + row*128 + ((gr ^ (row & 7)) << 4),
              g_a2h + ((size_t)e*64 + row)*ITR + j064 + gr*8);
        cp_commit();
    }

    int g = lane >> 2, tg = lane & 3;
    #pragma unroll
    for (int mf = 0; mf < 4; mf++){
        #pragma unroll
        for (int h = 0; h < 2; h++){
            int row = wm*64 + mf*16 + g + h*8;
            if (row >= rows) continue;
            __half* arow = g_act_h + (size_t)(m0 + row)*ITR + j064;
            #pragma unroll
            for (int nf = 0; nf < 4; nf++){
                float gate = acc[mf][nf][h*2 + 0];
                float up   = acc[mf][nf][h*2 + 1];
                float act = gate / (1.f + __expf(-gate)) * up;
                __half ah = __float2half(act);
                int c = wn*16 + nf*4 + tg;
                arow[c] = ah;
                *(__half*)(smc + row*128 + (((c >> 3) ^ (row & 7)) << 4) + (c & 7)*2) = ah;
            }
        }
    }
    cp_wait0();
    __syncthreads();

    // zd partial: C[128x32] = act_sm[128x64] @ da_sm[32x64]^T, atomically into g_zd_f
    {
        int wm2 = wid >> 1, wn2 = wid & 1;
        float zacc[2][2][4];
        #pragma unroll
        for (int i = 0; i < 2; i++)
            #pragma unroll
            for (int j = 0; j < 2; j++)
                #pragma unroll
                for (int k = 0; k < 4; k++) zacc[i][j][k] = 0.f;
        int ra = (lane & 7) + (((lane >> 3) & 1) << 3);
        int ka = lane >> 4;
        int rb = (lane & 7) + ((lane >> 4) << 3);
        int kb = (lane >> 3) & 1;
        #pragma unroll
        for (int ks = 0; ks < 4; ks++){
            uint32_t a[2][4], b4[4];
            #pragma unroll
            for (int mf = 0; mf < 2; mf++){
                int row = wm2*32 + mf*16 + ra;
                int kgr = ks*2 + ka;
                ldsm4(a[mf], smb + row*128 + ((kgr ^ (row & 7)) << 4));
            }
            {
                int row = wn2*16 + rb;
                int kgr = ks*2 + kb;
                ldsm4(b4, smb + 16384 + row*128 + ((kgr ^ (row & 7)) << 4));
            }
            #pragma unroll
            for (int mf = 0; mf < 2; mf++){
                mma16(zacc[mf][0], a[mf], b4 + 0);
                mma16(zacc[mf][1], a[mf], b4 + 2);
            }
        }
        #pragma unroll
        for (int mf = 0; mf < 2; mf++){
            #pragma unroll
            for (int h = 0; h < 2; h++){
                int row = wm2*32 + mf*16 + g + h*8;
                if (row >= rows) continue;
                float* zr = g_zd_f + (size_t)(m0 + row)*32;
                #pragma unroll
                for (int nf = 0; nf < 2; nf++){
                    int c = wn2*16 + nf*8 + 2*tg;
                    atomicAdd(zr + c,     zacc[mf][nf][h*2 + 0]);
                    atomicAdd(zr + c + 1, zacc[mf][nf][h*2 + 1]);
                }
            }
        }
    }
}

// ---------------- zd convert: adapter select + scale -> fp16 ----------------
__global__ void k_zdconv()
{
    int idx = blockIdx.x*blockDim.x + threadIdx.x;   // NPAIR*64 total
    int slot = idx >> 6;
    int c = idx & 63;
    if (slot >= NPAIR) return;
    int a = g_ad[slot];
    float sc = g_scale[slot];
    float v = 0.f;
    if (c < 16){ if (a == 0) v = sc * g_zd_f[(size_t)slot*32 + c]; }
    else if (c < 32){ if (a == 1) v = sc * g_zd_f[(size_t)slot*32 + c]; }
    g_zd_h[(size_t)slot*64 + c] = __float2half(v);
}

// ---------------- GEMM2 fill ----------------
__device__ __forceinline__ void fill2(uint32_t smb, int s, int kc, int tid,
                                      int e, int m0, int j0)
{
    uint32_t ab = smb + s*STAGEB;
    uint32_t bb = ab + 16384;
    #pragma unroll
    for (int q = 0; q < 4; q++){
        int G = tid + 256*q; int row = G >> 3, gr = G & 7;
        uint32_t off = row*128 + ((gr ^ (row & 7)) << 4);
        const __half* sa = (kc < 44)
            ? g_act_h + (size_t)(m0 + row)*ITR + kc*64 + gr*8
            : g_zd_h + (size_t)(m0 + row)*64 + gr*8;
        cpa16(ab + off, sa);
        const __half* sb = (kc < 44)
            ? g_wd_h + ((size_t)e*HID + j0 + row)*ITR + kc*64 + gr*8
            : g_bd_ext + ((size_t)e*HID + j0 + row)*64 + gr*8;
        cpa16(bb + off, sb);
    }
}

// ---------------- GEMM2: down proj + LoRA, weighted, atomic into out ----------------
__global__ __launch_bounds__(256, 2) void k_gemm2(float* __restrict__ out)
{
    int t = blockIdx.x;
    if (t >= g2_ntiles) return;
    int e = g2_e[t], m0 = g2_m0[t], rows = g2_rows[t];
    int j0 = blockIdx.y * BN;

    extern __shared__ char smc[];
    uint32_t smb = s2u(smc);
    __shared__ float s_wt[BM];
    __shared__ int   s_tok[BM];
    int tid = threadIdx.x, lane = tid & 31, wid = tid >> 5;
    int wm = wid & 1, wn = wid >> 1;
    if (tid < BM){
        int s = min(m0 + tid, NPAIR - 1);
        s_wt[tid] = g_w[s]; s_tok[tid] = g_tok[s];
    }

    float acc[4][4][4];
    #pragma unroll
    for (int i = 0; i < 4; i++)
        #pragma unroll
        for (int j = 0; j < 4; j++)
            #pragma unroll
            for (int k = 0; k < 4; k++) acc[i][j][k] = 0.f;

    fill2(smb, 0, 0, tid, e, m0, j0); cp_commit();
    fill2(smb, 1, 1, tid, e, m0, j0); cp_commit();
    int sC = 0, sF = 2;
    for (int kc = 0; kc < NK2; kc++){
        cp_wait1();
        __syncthreads();
        if (kc + 2 < NK2){ fill2(smb, sF, kc + 2, tid, e, m0, j0); }
        cp_commit();
        uint32_t st = smb + sC*STAGEB;
        stage_mma(st, st + 16384, lane, wm, wn, acc);
        sC = (sC == 2) ? 0 : sC + 1;
        sF = (sF == 2) ? 0 : sF + 1;
    }

    int g = lane >> 2, tg = lane & 3;
    #pragma unroll
    for (int mf = 0; mf < 4; mf++){
        #pragma unroll
        for (int h = 0; h < 2; h++){
            int row = wm*64 + mf*16 + g + h*8;
            if (row >= rows) continue;
            float w = s_wt[row];
            float* orow = out + (size_t)s_tok[row]*HID + j0;
            #pragma unroll
            for (int nf = 0; nf < 4; nf++){
                int c = wn*32 + nf*8 + 2*tg;
                atomicAdd(orow + c,     w * acc[mf][nf][h*2 + 0]);
                atomicAdd(orow + c + 1, w * acc[mf][nf][h*2 + 1]);
            }
        }
    }
}

// ---------------- launch ----------------
extern "C" void kernel_launch(void* const* d_in, const int* in_sizes, int n_in,
                              void* d_out, int out_size)
{
    const float* x        = (const float*)d_in[0];
    const int*   topk_ids = (const int*)  d_in[1];
    const float* topk_w   = (const float*)d_in[2];
    const float* gate_a   = (const float*)d_in[3];
    const float* gate_b   = (const float*)d_in[4];
    const float* up_a     = (const float*)d_in[5];
    const float* up_b     = (const float*)d_in[6];
    const float* down_a   = (const float*)d_in[7];
    const float* down_b   = (const float*)d_in[8];
    const int*   widx     = (const int*)  d_in[9];
    const int*   seq_lens = (const int*)  d_in[10];
    const int*   ranks    = (const int*)  d_in[11];
    const float* scalings = (const float*)d_in[12];
    const float* Wgu      = (const float*)d_in[13];
    const float* Wd       = (const float*)d_in[14];
    float* out = (float*)d_out;

    static cudaStream_t s_side = 0;
    static cudaEvent_t evFork = 0, evW = 0, evD = 0;
    static int s_init = 0;
    if (!s_init){
        cudaFuncSetAttribute(k_gemm1, cudaFuncAttributeMaxDynamicSharedMemorySize, SMEM_DYN);
        cudaFuncSetAttribute(k_gemm2, cudaFuncAttributeMaxDynamicSharedMemorySize, SMEM_DYN);
        cudaFuncSetAttribute(k_loraA, cudaFuncAttributeMaxDynamicSharedMemorySize, LSMEM);
        cudaStreamCreateWithFlags(&s_side, cudaStreamNonBlocking);
        cudaEventCreateWithFlags(&evFork, cudaEventDisableTiming);
        cudaEventCreateWithFlags(&evW, cudaEventDisableTiming);
        cudaEventCreateWithFlags(&evD, cudaEventDisableTiming);
        s_init = 1;
    }

    // fork side stream: weight conversions run concurrently with prep/loraA
    cudaEventRecord(evFork, 0);
    cudaStreamWaitEvent(s_side, evFork, 0);
    k_convgu<<<1184, 256, 0, s_side>>>(Wgu);
    cudaEventRecord(evW, s_side);
    k_convwd<<<1184, 256, 0, s_side>>>(Wd);
    cudaEventRecord(evD, s_side);

    // main stream
    k_setup<<<1, 256>>>(topk_ids, topk_w, widx, seq_lens, scalings);
    k_preall<<<2048, 256>>>(x, gate_a, up_a, down_a,
                            gate_b, up_b, down_b, ranks, out);
    k_loraA<<<MAXT, 256, LSMEM>>>();
    cudaStreamWaitEvent(0, evW, 0);
    k_gemm1<<<dim3(MAXT, NCT1), 256, SMEM_DYN>>>();
    k_zdconv<<<NPAIR*64/256, 256>>>();
    cudaStreamWaitEvent(0, evD, 0);
    k_gemm2<<<dim3(MAXT, NCT2), 256, SMEM_DYN>>>(out);
}

// round 15
// speedup vs baseline: 1.3717x; 1.3717x over previous
#include <cuda_runtime.h>
#include <cuda_fp16.h>
#include <math.h>
#include <stdint.h>

// ---------------- problem constants ----------------
#define NTOK  2048
#define HID   1024
#define ITR   2816
#define NEXP  8
#define NADP  2
#define RNK   16
#define TOPK  2
#define NSEQ  8
#define NPAIR (NTOK*TOPK)        // 4096
#define NPAD  (NPAIR + 128)

// ---------------- GEMM tiling (mma.sync m16n8k16 fp16) ----------------
#define BM 128
#define BN 128
#define STAGEB 32768              // A tile 16KB + B tile 16KB
#define NSTG 3
#define SMEM_DYN (NSTG*STAGEB)    // 98304
#define NK1 17                    // 16 real + 1 lora-ext
#define NK2 45                    // 44 real + 1 lora-ext
#define MAXT (NPAIR/BM + NEXP)    // 40
#define NCT1 (ITR/64)             // 44
#define NCT2 (HID/BN)             // 8
#define NEY  4                    // extra y-rows in gemm1 doing Wd conversion
// lora-A GEMM (N=64)
#define LSTAGE 24576              // A 16KB + B 8KB
#define LSMEM (NSTG*LSTAGE)       // 73728
#define NCV1 216                  // extra blocks in loraA doing Wgu conversion

// ---------------- device scratch ----------------
__device__ int   g_tok[NPAIR];
__device__ float g_w[NPAIR];
__device__ int   g_ad[NPAIR];
__device__ float g_scale[NPAIR];
__device__ int   g2_ntiles;
__device__ int   g2_e[MAXT];
__device__ int   g2_m0[MAXT];
__device__ int   g2_rows[MAXT];
__device__ __align__(16) __half g_xg_h[(size_t)NPAD*HID];
__device__ __align__(16) __half g_act_h[(size_t)NPAD*ITR];
__device__ __align__(16) __half g_zgu_h[(size_t)NPAD*64];
__device__ __align__(16) __half g_zd_h[(size_t)NPAD*64];
__device__ float g_zd_f[(size_t)NPAIR*32];
__device__ __align__(16) __half g_wgu_h[(size_t)NEXP*2*ITR*HID];
__device__ __align__(16) __half g_wd_h[(size_t)NEXP*HID*ITR];
__device__ __align__(16) __half g_bg_ext[(size_t)NEXP*2*ITR*64];
__device__ __align__(16) __half g_bd_ext[(size_t)NEXP*HID*64];
__device__ __align__(16) __half g_a1h[(size_t)NEXP*64*HID];   // [e][ga0|ua0|ga1|ua1][HID]
__device__ __align__(16) __half g_a2h[(size_t)NEXP*64*ITR];   // [e][da0|da1|zeros][ITR]

// ---------------- PTX helpers ----------------
__device__ __forceinline__ uint32_t s2u(const void* p){
    uint32_t a;
    asm("{ .reg .u64 t; cvta.to.shared.u64 t, %1; cvt.u32.u64 %0, t; }":"=r"(a):"l"(p));
    return a;
}
__device__ __forceinline__ void cpa16(uint32_t dst, const void* src){
    asm volatile("cp.async.cg.shared.global [%0], [%1], 16;" :: "r"(dst), "l"(src));
}
__device__ __forceinline__ void cp_commit(){ asm volatile("cp.async.commit_group;":::"memory"); }
__device__ __forceinline__ void cp_wait1(){ asm volatile("cp.async.wait_group 1;":::"memory"); }
__device__ __forceinline__ void cp_wait0(){ asm volatile("cp.async.wait_group 0;":::"memory"); }
__device__ __forceinline__ void ldsm4(uint32_t* r, uint32_t addr){
    asm volatile("ldmatrix.sync.aligned.m8n8.x4.shared.b16 {%0,%1,%2,%3}, [%4];"
      : "=r"(r[0]),"=r"(r[1]),"=r"(r[2]),"=r"(r[3]) : "r"(addr));
}
__device__ __forceinline__ void mma16(float* c, const uint32_t* a, const uint32_t* b){
    asm volatile("mma.sync.aligned.m16n8k16.row.col.f32.f16.f16.f32 "
      "{%0,%1,%2,%3},{%4,%5,%6,%7},{%8,%9},{%0,%1,%2,%3};"
      : "+f"(c[0]),"+f"(c[1]),"+f"(c[2]),"+f"(c[3])
      : "r"(a[0]),"r"(a[1]),"r"(a[2]),"r"(a[3]),"r"(b[0]),"r"(b[1]));
}
// store 8 contiguous fp32 -> 8 fp16 at dst (16B)
__device__ __forceinline__ void store8h(__half* dst, const float* __restrict__ src){
    float4 v0 = *(const float4*)src;
    float4 v1 = *(const float4*)(src + 4);
    __half2 h[4];
    h[0] = __float22half2_rn(make_float2(v0.x, v0.y));
    h[1] = __float22half2_rn(make_float2(v0.z, v0.w));
    h[2] = __float22half2_rn(make_float2(v1.x, v1.y));
    h[3] = __float22half2_rn(make_float2(v1.z, v1.w));
    *(uint4*)dst = *(uint4*)h;
}
__device__ __forceinline__ void store8z(__half* dst){
    *(uint4*)dst = make_uint4(0u, 0u, 0u, 0u);
}

// ---------------- BN=128 mainloop compute ----------------
__device__ __forceinline__ void stage_mma(uint32_t smA, uint32_t smB,
                                          int lane, int wm, int wn,
                                          float (*acc)[4][4])
{
    int ra = (lane & 7) + (((lane >> 3) & 1) << 3);
    int ka = lane >> 4;
    int rb = (lane & 7) + ((lane >> 4) << 3);
    int kb = (lane >> 3) & 1;
    #pragma unroll
    for (int ks = 0; ks < 4; ks++){
        uint32_t a[4][4], b[2][4];
        #pragma unroll
        for (int mf = 0; mf < 4; mf++){
            int row = wm*64 + mf*16 + ra;
            int kgr = ks*2 + ka;
            ldsm4(a[mf], smA + row*128 + ((kgr ^ (row & 7)) << 4));
        }
        #pragma unroll
        for (int nfp = 0; nfp < 2; nfp++){
            int row = wn*32 + nfp*16 + rb;
            int kgr = ks*2 + kb;
            ldsm4(b[nfp], smB + row*128 + ((kgr ^ (row & 7)) << 4));
        }
        #pragma unroll
        for (int mf = 0; mf < 4; mf++){
            mma16(acc[mf][0], a[mf], b[0] + 0);
            mma16(acc[mf][1], a[mf], b[0] + 2);
            mma16(acc[mf][2], a[mf], b[1] + 0);
            mma16(acc[mf][3], a[mf], b[1] + 2);
        }
    }
}

// ---------------- BN=64 mainloop compute (lora-A GEMM) ----------------
__device__ __forceinline__ void stage_mma64(uint32_t smA, uint32_t smB,
                                            int lane, int wm, int wn,
                                            float (*acc)[4][4])   // acc[2][4][4]
{
    int ra = (lane & 7) + (((lane >> 3) & 1) << 3);
    int ka = lane >> 4;
    int rb = (lane & 7) + ((lane >> 4) << 3);
    int kb = (lane >> 3) & 1;
    #pragma unroll
    for (int ks = 0; ks < 4; ks++){
        uint32_t a[2][4], b[2][4];
        #pragma unroll
        for (int mf = 0; mf < 2; mf++){
            int row = wm*32 + mf*16 + ra;
            int kgr = ks*2 + ka;
            ldsm4(a[mf], smA + row*128 + ((kgr ^ (row & 7)) << 4));
        }
        #pragma unroll
        for (int nfp = 0; nfp < 2; nfp++){
            int row = wn*32 + nfp*16 + rb;
            int kgr = ks*2 + kb;
            ldsm4(b[nfp], smB + row*128 + ((kgr ^ (row & 7)) << 4));
        }
        #pragma unroll
        for (int mf = 0; mf < 2; mf++){
            mma16(acc[mf][0], a[mf], b[0] + 0);
            mma16(acc[mf][1], a[mf], b[0] + 2);
            mma16(acc[mf][2], a[mf], b[1] + 0);
            mma16(acc[mf][3], a[mf], b[1] + 2);
        }
    }
}

// ---------------- setup ----------------
__global__ void k_setup(const int* __restrict__ topk_ids, const float* __restrict__ topk_w,
                        const int* __restrict__ widx, const int* __restrict__ seq_lens,
                        const float* __restrict__ scalings)
{
    __shared__ int cnt[NEXP*NADP], off[NEXP*NADP], cur[NEXP*NADP], cum[NSEQ];
    int tid = threadIdx.x;
    if (tid < NEXP*NADP) cnt[tid] = 0;
    __syncthreads();
    if (tid == 0){ int c = 0; for (int s = 0; s < NSEQ; s++){ c += seq_lens[s]; cum[s] = c; } }
    __syncthreads();
    for (int p = tid; p < NPAIR; p += blockDim.x){
        int n = p / TOPK; int e = topk_ids[p];
        int s = 0; while (n >= cum[s]) s++;
        atomicAdd(&cnt[e*NADP + widx[s]], 1);
    }
    __syncthreads();
    if (tid == 0){
        int acc = 0;
        for (int k = 0; k < NEXP*NADP; k++){ off[k] = acc; cur[k] = acc; acc += cnt[k]; }
        int nt = 0;
        for (int e = 0; e < NEXP; e++){
            int base = off[e*NADP];
            int c = cnt[e*NADP] + cnt[e*NADP+1];
            for (int r0 = 0; r0 < c; r0 += BM){
                g2_e[nt] = e; g2_m0[nt] = base + r0; g2_rows[nt] = min(BM, c - r0); nt++;
            }
        }
        g2_ntiles = nt;
    }
    __syncthreads();
    for (int p = tid; p < NPAIR; p += blockDim.x){
        int n = p / TOPK; int e = topk_ids[p];
        int s = 0; while (n >= cum[s]) s++;
        int a = widx[s];
        int slot = atomicAdd(&cur[e*NADP + a], 1);
        g_tok[slot] = n; g_w[slot] = topk_w[p]; g_ad[slot] = a;
        g_scale[slot] = scalings[a];
    }
}

// ---------------- prep: lora tiles (vectorized) + gather + zero ----------------
__global__ void k_preall(const float* __restrict__ x,
                         const float* __restrict__ gate_a, const float* __restrict__ up_a,
                         const float* __restrict__ down_a,
                         const float* __restrict__ gb, const float* __restrict__ ub,
                         const float* __restrict__ db, const int* __restrict__ ranks,
                         float* __restrict__ out)
{
    size_t stride = (size_t)gridDim.x*blockDim.x;
    size_t tid0 = (size_t)blockIdx.x*blockDim.x + threadIdx.x;
    int r0 = ranks[0], r1 = ranks[1];
    // gather x rows to fp16 by slot
    {
        const size_t n = (size_t)NPAIR*(HID/4);
        for (size_t i = tid0; i < n; i += stride){
            int slot = (int)(i >> 8);
            int c = (int)(i & 255);
            float4 v = ((const float4*)(x + (size_t)g_tok[slot]*HID))[c];
            __half2* xh = (__half2*)(g_xg_h + (size_t)slot*HID);
            xh[2*c]   = __float22half2_rn(make_float2(v.x, v.y));
            xh[2*c+1] = __float22half2_rn(make_float2(v.z, v.w));
        }
    }
    // zero out + zd_f
    {
        const size_t n = (size_t)NTOK*HID/4;
        for (size_t i = tid0; i < n; i += stride)
            ((float4*)out)[i] = make_float4(0.f, 0.f, 0.f, 0.f);
        const size_t nz = (size_t)NPAIR*32/4;
        for (size_t i = tid0; i < nz; i += stride)
            ((float4*)g_zd_f)[i] = make_float4(0.f, 0.f, 0.f, 0.f);
    }
    // bg_ext: rows = NEXP*2*ITR, 8 blocks of 8 halfs per row
    {
        const size_t n1 = (size_t)NEXP*2*ITR*8;
        for (size_t i = tid0; i < n1; i += stride){
            int blk = (int)(i & 7);                 // 8-half block index
            size_t R = i >> 3;
            int e = (int)(R / (2*ITR));
            int r = (int)(R % (2*ITR));
            int j = r >> 1;
            __half* dst = g_bg_ext + R*64 + blk*8;
            int c0 = blk*8;
            const float* src = 0;
            if (!(r & 1)){  // gate row
                if (c0 < 16)                 src = gb + ((size_t)(0*NEXP + e)*ITR + j)*RNK + c0;
                else if (c0 >= 32 && c0 < 48) src = gb + ((size_t)(1*NEXP + e)*ITR + j)*RNK + (c0 - 32);
            } else {        // up row
                if (c0 >= 16 && c0 < 32)     src = ub + ((size_t)(0*NEXP + e)*ITR + j)*RNK + (c0 - 16);
                else if (c0 >= 48)           src = ub + ((size_t)(1*NEXP + e)*ITR + j)*RNK + (c0 - 48);
            }
            if (src) store8h(dst, src); else store8z(dst);
        }
    }
    // bd_ext: rows = NEXP*HID
    {
        const size_t n2 = (size_t)NEXP*HID*8;
        for (size_t i = tid0; i < n2; i += stride){
            int blk = (int)(i & 7);
            size_t R = i >> 3;
            int e = (int)(R >> 10);
            int h = (int)(R & (HID-1));
            __half* dst = g_bd_ext + R*64 + blk*8;
            int c0 = blk*8;
            const float* src = 0;
            if (c0 < 16)      src = db + ((size_t)(0*NEXP + e)*HID + h)*RNK + c0;
            else if (c0 < 32) src = db + ((size_t)(1*NEXP + e)*HID + h)*RNK + (c0 - 16);
            if (src) store8h(dst, src); else store8z(dst);
        }
    }
    // a1h: rows = NEXP*64, HID cols -> HID/8 blocks per row
    {
        const size_t n3 = (size_t)NEXP*64*(HID/8);
        for (size_t i = tid0; i < n3; i += stride){
            int blk = (int)(i & (HID/8 - 1));
            size_t R = i >> 7;                    // HID/8 = 128
            int e = (int)(R >> 6);
            int r = (int)(R & 63);
            int aidx = r >> 5, type = (r >> 4) & 1, rr = r & 15;
            int rk = aidx ? r1 : r0;
            __half* dst = g_a1h + R*HID + blk*8;
            if (rr < rk){
                const float* src = (type == 0 ? gate_a : up_a)
                    + ((size_t)((aidx*NEXP + e)*RNK) + rr)*HID + blk*8;
                store8h(dst, src);
            } else store8z(dst);
        }
    }
    // a2h: rows = NEXP*64, ITR cols -> ITR/8 blocks per row
    {
        const size_t n4 = (size_t)NEXP*64*(ITR/8);
        for (size_t i = tid0; i < n4; i += stride){
            int blk = (int)(i % (ITR/8));
            size_t R = i / (ITR/8);
            int e = (int)(R >> 6);
            int r = (int)(R & 63);
            __half* dst = g_a2h + R*ITR + blk*8;
            bool live = false;
            const float* src = 0;
            if (r < 32){
                int aidx = r >> 4, rr = r & 15;
                int rk = aidx ? r1 : r0;
                if (rr < rk){
                    live = true;
                    src = down_a + ((size_t)((aidx*NEXP + e)*RNK) + rr)*ITR + blk*8;
                }
            }
            if (live) store8h(dst, src); else store8z(dst);
        }
    }
}

// ---------------- lora-A GEMM fill ----------------
__device__ __forceinline__ void fillL(uint32_t smb, int s, int kc, int tid,
                                      const __half* Ab, int lda, const __half* Bb)
{
    uint32_t ab = smb + s*LSTAGE;
    uint32_t bb = ab + 16384;
    #pragma unroll
    for (int q = 0; q < 4; q++){
        int G = tid + 256*q; int row = G >> 3, gr = G & 7;
        cpa16(ab + row*128 + ((gr ^ (row & 7)) << 4), Ab + (size_t)row*lda + kc*64 + gr*8);
    }
    #pragma unroll
    for (int q = 0; q < 2; q++){
        int G = tid + 256*q; int row = G >> 3, gr = G & 7;
        cpa16(bb + row*128 + ((gr ^ (row & 7)) << 4), Bb + (size_t)row*lda + kc*64 + gr*8);
    }
}

// ---------------- lora-A GEMM for zgu; extra blocks convert Wgu ----------------
__global__ __launch_bounds__(256, 2) void k_loraA(const float* __restrict__ wgu)
{
    int t = blockIdx.x;
    if (t >= MAXT){
        size_t wi = (size_t)(t - MAXT)*blockDim.x + threadIdx.x;
        size_t nw = (size_t)(gridDim.x - MAXT)*blockDim.x;
        const size_t n1 = (size_t)NEXP*2*ITR*HID/4;
        __half2* o1 = (__half2*)g_wgu_h;
        for (size_t i = wi; i < n1; i += nw){
            float4 v = ((const float4*)wgu)[i];
            o1[2*i]   = __float22half2_rn(make_float2(v.x, v.y));
            o1[2*i+1] = __float22half2_rn(make_float2(v.z, v.w));
        }
        return;
    }
    if (t >= g2_ntiles) return;
    int e = g2_e[t], m0 = g2_m0[t], rows = g2_rows[t];

    const __half* Ab = g_xg_h + (size_t)m0*HID;
    const __half* Bb = g_a1h + (size_t)e*64*HID;
    const int lda = HID, nk = 16;

    extern __shared__ char smc[];
    uint32_t smb = s2u(smc);
    int tid = threadIdx.x, lane = tid & 31, wid = tid >> 5;
    int wm = wid & 3, wn = wid >> 2;

    float acc[2][4][4];
    #pragma unroll
    for (int i = 0; i < 2; i++)
        #pragma unroll
        for (int j = 0; j < 4; j++)
            #pragma unroll
            for (int k = 0; k < 4; k++) acc[i][j][k] = 0.f;

    fillL(smb, 0, 0, tid, Ab, lda, Bb); cp_commit();
    fillL(smb, 1, 1, tid, Ab, lda, Bb); cp_commit();
    int sC = 0, sF = 2;
    for (int kc = 0; kc < nk; kc++){
        cp_wait1();
        __syncthreads();
        if (kc + 2 < nk){ fillL(smb, sF, kc + 2, tid, Ab, lda, Bb); }
        cp_commit();
        uint32_t st = smb + sC*LSTAGE;
        stage_mma64(st, st + 16384, lane, wm, wn, acc);
        sC = (sC == 2) ? 0 : sC + 1;
        sF = (sF == 2) ? 0 : sF + 1;
    }

    int g = lane >> 2, tg = lane & 3;
    #pragma unroll
    for (int mf = 0; mf < 2; mf++){
        #pragma unroll
        for (int h = 0; h < 2; h++){
            int row = wm*32 + mf*16 + g + h*8;
            if (row >= rows) continue;
            int slot = m0 + row;
            int a = g_ad[slot];
            float sc = g_scale[slot];
            __half* orow = g_zgu_h + (size_t)slot*64;
            #pragma unroll
            for (int nf = 0; nf < 4; nf++){
                #pragma unroll
                for (int p = 0; p < 2; p++){
                    int c = wn*32 + nf*8 + 2*tg + p;
                    float v = acc[mf][nf][h*2 + p];
                    bool keep = (a == 0) ? (c < 32) : (c >= 32);
                    orow[c] = __float2half(keep ? sc*v : 0.f);
                }
            }
        }
    }
}

// ---------------- GEMM1 fill ----------------
__device__ __forceinline__ void fill1(uint32_t smb, int s, int kc, int tid,
                                      int e, int m0, int j064)
{
    uint32_t ab = smb + s*STAGEB;
    uint32_t bb = ab + 16384;
    #pragma unroll
    for (int q = 0; q < 4; q++){
        int G = tid + 256*q; int row = G >> 3, gr = G & 7;
        uint32_t off = row*128 + ((gr ^ (row & 7)) << 4);
        const __half* sa = (kc < 16)
            ? g_xg_h + (size_t)(m0 + row)*HID + kc*64 + gr*8
            : g_zgu_h + (size_t)(m0 + row)*64 + gr*8;
        cpa16(ab + off, sa);
        const __half* sb;
        if (kc < 16){
            int sr = ((row & 1) ? ITR : 0) + j064 + (row >> 1);
            sb = g_wgu_h + ((size_t)e*(2*ITR) + sr)*HID + kc*64 + gr*8;
        } else {
            sb = g_bg_ext + ((size_t)e*(2*ITR) + 2*j064 + row)*64 + gr*8;
        }
        cpa16(bb + off, sb);
    }
}

// ---------------- GEMM1: gate/up + LoRA + SiLU -> act; zd partials; extra y convert Wd ----------------
__global__ __launch_bounds__(256, 2) void k_gemm1(const float* __restrict__ wd)
{
    int t = blockIdx.x;
    if (blockIdx.y >= NCT1){
        size_t wi = ((size_t)(blockIdx.y - NCT1)*MAXT + t)*blockDim.x + threadIdx.x;
        size_t nw = (size_t)NEY*MAXT*blockDim.x;
        const size_t n2 = (size_t)NEXP*HID*ITR/4;
        __half2* o2 = (__half2*)g_wd_h;
        for (size_t i = wi; i < n2; i += nw){
            float4 v = ((const float4*)wd)[i];
            o2[2*i]   = __float22half2_rn(make_float2(v.x, v.y));
            o2[2*i+1] = __float22half2_rn(make_float2(v.z, v.w));
        }
        return;
    }
    if (t >= g2_ntiles) return;
    int e = g2_e[t], m0 = g2_m0[t], rows = g2_rows[t];
    int j064 = blockIdx.y * 64;

    extern __shared__ char smc[];
    uint32_t smb = s2u(smc);
    int tid = threadIdx.x, lane = tid & 31, wid = tid >> 5;
    int wm = wid & 1, wn = wid >> 1;

    float acc[4][4][4];
    #pragma unroll
    for (int i = 0; i < 4; i++)
        #pragma unroll
        for (int j = 0; j < 4; j++)
            #pragma unroll
            for (int k = 0; k < 4; k++) acc[i][j][k] = 0.f;

    fill1(smb, 0, 0, tid, e, m0, j064); cp_commit();
    fill1(smb, 1, 1, tid, e, m0, j064); cp_commit();
    int sC = 0, sF = 2;
    for (int kc = 0; kc < NK1; kc++){
        cp_wait1();
        __syncthreads();
        if (kc + 2 < NK1){ fill1(smb, sF, kc + 2, tid, e, m0, j064); }
        cp_commit();
        uint32_t st = smb + sC*STAGEB;
        stage_mma(st, st + 16384, lane, wm, wn, acc);
        sC = (sC == 2) ? 0 : sC + 1;
        sF = (sF == 2) ? 0 : sF + 1;
    }

    // fetch da tile for zd partial GEMM: rows 0..31 of g_a2h[e], K slice j064..j064+63
    {
        int row = tid >> 3, gr = tid & 7;  // 32 rows x 8 granules = 256
        cpa16(smb + 16384 + row*128 + ((gr ^ (row & 7)) << 4),
              g_a2h + ((size_t)e*64 + row)*ITR + j064 + gr*8);
        cp_commit();
    }

    int g = lane >> 2, tg = lane & 3;
    #pragma unroll
    for (int mf = 0; mf < 4; mf++){
        #pragma unroll
        for (int h = 0; h < 2; h++){
            int row = wm*64 + mf*16 + g + h*8;
            if (row >= rows) continue;
            __half* arow = g_act_h + (size_t)(m0 + row)*ITR + j064;
            #pragma unroll
            for (int nf = 0; nf < 4; nf++){
                float gate = acc[mf][nf][h*2 + 0];
                float up   = acc[mf][nf][h*2 + 1];
                float act = gate / (1.f + __expf(-gate)) * up;
                __half ah = __float2half(act);
                int c = wn*16 + nf*4 + tg;
                arow[c] = ah;
                *(__half*)(smc + row*128 + (((c >> 3) ^ (row & 7)) << 4) + (c & 7)*2) = ah;
            }
        }
    }
    cp_wait0();
    __syncthreads();

    // zd partial: C[128x32] = act_sm[128x64] @ da_sm[32x64]^T, atomically into g_zd_f
    {
        int wm2 = wid >> 1, wn2 = wid & 1;
        float zacc[2][2][4];
        #pragma unroll
        for (int i = 0; i < 2; i++)
            #pragma unroll
            for (int j = 0; j < 2; j++)
                #pragma unroll
                for (int k = 0; k < 4; k++) zacc[i][j][k] = 0.f;
        int ra = (lane & 7) + (((lane >> 3) & 1) << 3);
        int ka = lane >> 4;
        int rb = (lane & 7) + ((lane >> 4) << 3);
        int kb = (lane >> 3) & 1;
        #pragma unroll
        for (int ks = 0; ks < 4; ks++){
            uint32_t a[2][4], b4[4];
            #pragma unroll
            for (int mf = 0; mf < 2; mf++){
                int row = wm2*32 + mf*16 + ra;
                int kgr = ks*2 + ka;
                ldsm4(a[mf], smb + row*128 + ((kgr ^ (row & 7)) << 4));
            }
            {
                int row = wn2*16 + rb;
                int kgr = ks*2 + kb;
                ldsm4(b4, smb + 16384 + row*128 + ((kgr ^ (row & 7)) << 4));
            }
            #pragma unroll
            for (int mf = 0; mf < 2; mf++){
                mma16(zacc[mf][0], a[mf], b4 + 0);
                mma16(zacc[mf][1], a[mf], b4 + 2);
            }
        }
        #pragma unroll
        for (int mf = 0; mf < 2; mf++){
            #pragma unroll
            for (int h = 0; h < 2; h++){
                int row = wm2*32 + mf*16 + g + h*8;
                if (row >= rows) continue;
                float* zr = g_zd_f + (size_t)(m0 + row)*32;
                #pragma unroll
                for (int nf = 0; nf < 2; nf++){
                    int c = wn2*16 + nf*8 + 2*tg;
                    atomicAdd(zr + c,     zacc[mf][nf][h*2 + 0]);
                    atomicAdd(zr + c + 1, zacc[mf][nf][h*2 + 1]);
                }
            }
        }
    }
}

// ---------------- zd convert: adapter select + scale -> fp16 ----------------
__global__ void k_zdconv()
{
    int idx = blockIdx.x*blockDim.x + threadIdx.x;   // NPAIR*64 total
    int slot = idx >> 6;
    int c = idx & 63;
    if (slot >= NPAIR) return;
    int a = g_ad[slot];
    float sc = g_scale[slot];
    float v = 0.f;
    if (c < 16){ if (a == 0) v = sc * g_zd_f[(size_t)slot*32 + c]; }
    else if (c < 32){ if (a == 1) v = sc * g_zd_f[(size_t)slot*32 + c]; }
    g_zd_h[(size_t)slot*64 + c] = __float2half(v);
}

// ---------------- GEMM2 fill ----------------
__device__ __forceinline__ void fill2(uint32_t smb, int s, int kc, int tid,
                                      int e, int m0, int j0)
{
    uint32_t ab = smb + s*STAGEB;
    uint32_t bb = ab + 16384;
    #pragma unroll
    for (int q = 0; q < 4; q++){
        int G = tid + 256*q; int row = G >> 3, gr = G & 7;
        uint32_t off = row*128 + ((gr ^ (row & 7)) << 4);
        const __half* sa = (kc < 44)
            ? g_act_h + (size_t)(m0 + row)*ITR + kc*64 + gr*8
            : g_zd_h + (size_t)(m0 + row)*64 + gr*8;
        cpa16(ab + off, sa);
        const __half* sb = (kc < 44)
            ? g_wd_h + ((size_t)e*HID + j0 + row)*ITR + kc*64 + gr*8
            : g_bd_ext + ((size_t)e*HID + j0 + row)*64 + gr*8;
        cpa16(bb + off, sb);
    }
}

// ---------------- GEMM2: down proj + LoRA, weighted, atomic into out ----------------
__global__ __launch_bounds__(256, 2) void k_gemm2(float* __restrict__ out)
{
    int t = blockIdx.x;
    if (t >= g2_ntiles) return;
    int e = g2_e[t], m0 = g2_m0[t], rows = g2_rows[t];
    int j0 = blockIdx.y * BN;

    extern __shared__ char smc[];
    uint32_t smb = s2u(smc);
    __shared__ float s_wt[BM];
    __shared__ int   s_tok[BM];
    int tid = threadIdx.x, lane = tid & 31, wid = tid >> 5;
    int wm = wid & 1, wn = wid >> 1;
    if (tid < BM){
        int s = min(m0 + tid, NPAIR - 1);
        s_wt[tid] = g_w[s]; s_tok[tid] = g_tok[s];
    }

    float acc[4][4][4];
    #pragma unroll
    for (int i = 0; i < 4; i++)
        #pragma unroll
        for (int j = 0; j < 4; j++)
            #pragma unroll
            for (int k = 0; k < 4; k++) acc[i][j][k] = 0.f;

    fill2(smb, 0, 0, tid, e, m0, j0); cp_commit();
    fill2(smb, 1, 1, tid, e, m0, j0); cp_commit();
    int sC = 0, sF = 2;
    for (int kc = 0; kc < NK2; kc++){
        cp_wait1();
        __syncthreads();
        if (kc + 2 < NK2){ fill2(smb, sF, kc + 2, tid, e, m0, j0); }
        cp_commit();
        uint32_t st = smb + sC*STAGEB;
        stage_mma(st, st + 16384, lane, wm, wn, acc);
        sC = (sC == 2) ? 0 : sC + 1;
        sF = (sF == 2) ? 0 : sF + 1;
    }

    int g = lane >> 2, tg = lane & 3;
    #pragma unroll
    for (int mf = 0; mf < 4; mf++){
        #pragma unroll
        for (int h = 0; h < 2; h++){
            int row = wm*64 + mf*16 + g + h*8;
            if (row >= rows) continue;
            float w = s_wt[row];
            float* orow = out + (size_t)s_tok[row]*HID + j0;
            #pragma unroll
            for (int nf = 0; nf < 4; nf++){
                int c = wn*32 + nf*8 + 2*tg;
                atomicAdd(orow + c,     w * acc[mf][nf][h*2 + 0]);
                atomicAdd(orow + c + 1, w * acc[mf][nf][h*2 + 1]);
            }
        }
    }
}

// ---------------- launch ----------------
extern "C" void kernel_launch(void* const* d_in, const int* in_sizes, int n_in,
                              void* d_out, int out_size)
{
    const float* x        = (const float*)d_in[0];
    const int*   topk_ids = (const int*)  d_in[1];
    const float* topk_w   = (const float*)d_in[2];
    const float* gate_a   = (const float*)d_in[3];
    const float* gate_b   = (const float*)d_in[4];
    const float* up_a     = (const float*)d_in[5];
    const float* up_b     = (const float*)d_in[6];
    const float* down_a   = (const float*)d_in[7];
    const float* down_b   = (const float*)d_in[8];
    const int*   widx     = (const int*)  d_in[9];
    const int*   seq_lens = (const int*)  d_in[10];
    const int*   ranks    = (const int*)  d_in[11];
    const float* scalings = (const float*)d_in[12];
    const float* Wgu      = (const float*)d_in[13];
    const float* Wd       = (const float*)d_in[14];
    float* out = (float*)d_out;

    static int s_attr_done = 0;
    if (!s_attr_done){
        cudaFuncSetAttribute(k_gemm1, cudaFuncAttributeMaxDynamicSharedMemorySize, SMEM_DYN);
        cudaFuncSetAttribute(k_gemm2, cudaFuncAttributeMaxDynamicSharedMemorySize, SMEM_DYN);
        cudaFuncSetAttribute(k_loraA, cudaFuncAttributeMaxDynamicSharedMemorySize, LSMEM);
        s_attr_done = 1;
    }

    k_setup<<<1, 256>>>(topk_ids, topk_w, widx, seq_lens, scalings);
    k_preall<<<2048, 256>>>(x, gate_a, up_a, down_a,
                            gate_b, up_b, down_b, ranks, out);
    k_loraA<<<MAXT + NCV1, 256, LSMEM>>>(Wgu);
    k_gemm1<<<dim3(MAXT, NCT1 + NEY), 256, SMEM_DYN>>>(Wd);
    k_zdconv<<<NPAIR*64/256, 256>>>();
    k_gemm2<<<dim3(MAXT, NCT2), 256, SMEM_DYN>>>(out);
}

// round 16
// speedup vs baseline: 1.3790x; 1.0054x over previous
#include <cuda_runtime.h>
#include <cuda_fp16.h>
#include <math.h>
#include <stdint.h>

// ---------------- problem constants ----------------
#define NTOK  2048
#define HID   1024
#define ITR   2816
#define NEXP  8
#define NADP  2
#define RNK   16
#define TOPK  2
#define NSEQ  8
#define NPAIR (NTOK*TOPK)        // 4096
#define NPAD  (NPAIR + 128)

// ---------------- GEMM tiling (mma.sync m16n8k16 fp16) ----------------
#define BM 128
#define BN 128
#define STAGEB 32768              // A tile 16KB + B tile 16KB
#define NSTG 3
#define SMEM_DYN (NSTG*STAGEB)    // 98304
#define NK1 17                    // 16 real + 1 lora-ext
#define NK2 45                    // 44 real + 1 lora-ext
#define MAXT (NPAIR/BM + NEXP)    // 40
#define NCT1 (ITR/64)             // 44
#define NCT2 (HID/BN)             // 8
#define NEY  4                    // extra y-rows in gemm1 doing Wd conversion
// lora-A GEMM (N=64)
#define LSTAGE 24576              // A 16KB + B 8KB
#define LSMEM (NSTG*LSTAGE)       // 73728
#define NCV1 552                  // extra blocks in loraA doing Wgu conversion (40+552 = 2 waves)

// ---------------- device scratch ----------------
__device__ int   g_tok[NPAIR];
__device__ float g_w[NPAIR];
__device__ int   g_ad[NPAIR];
__device__ float g_scale[NPAIR];
__device__ int   g2_ntiles;
__device__ int   g2_e[MAXT];
__device__ int   g2_m0[MAXT];
__device__ int   g2_rows[MAXT];
__device__ __align__(16) __half g_xg_h[(size_t)NPAD*HID];
__device__ __align__(16) __half g_act_h[(size_t)NPAD*ITR];
__device__ __align__(16) __half g_zgu_h[(size_t)NPAD*64];
__device__ __align__(16) __half g_zd_h[(size_t)NPAD*64];
__device__ float g_zd_f[(size_t)NPAIR*32];
__device__ __align__(16) __half g_wgu_h[(size_t)NEXP*2*ITR*HID];
__device__ __align__(16) __half g_wd_h[(size_t)NEXP*HID*ITR];
__device__ __align__(16) __half g_bg_ext[(size_t)NEXP*2*ITR*64];
__device__ __align__(16) __half g_bd_ext[(size_t)NEXP*HID*64];
__device__ __align__(16) __half g_a1h[(size_t)NEXP*64*HID];   // [e][ga0|ua0|ga1|ua1][HID]
__device__ __align__(16) __half g_a2h[(size_t)NEXP*64*ITR];   // [e][da0|da1|zeros][ITR]

// ---------------- PTX helpers ----------------
__device__ __forceinline__ uint32_t s2u(const void* p){
    uint32_t a;
    asm("{ .reg .u64 t; cvta.to.shared.u64 t, %1; cvt.u32.u64 %0, t; }":"=r"(a):"l"(p));
    return a;
}
__device__ __forceinline__ void cpa16(uint32_t dst, const void* src){
    asm volatile("cp.async.cg.shared.global [%0], [%1], 16;" :: "r"(dst), "l"(src));
}
__device__ __forceinline__ void cp_commit(){ asm volatile("cp.async.commit_group;":::"memory"); }
__device__ __forceinline__ void cp_wait1(){ asm volatile("cp.async.wait_group 1;":::"memory"); }
__device__ __forceinline__ void cp_wait0(){ asm volatile("cp.async.wait_group 0;":::"memory"); }
__device__ __forceinline__ void ldsm4(uint32_t* r, uint32_t addr){
    asm volatile("ldmatrix.sync.aligned.m8n8.x4.shared.b16 {%0,%1,%2,%3}, [%4];"
      : "=r"(r[0]),"=r"(r[1]),"=r"(r[2]),"=r"(r[3]) : "r"(addr));
}
__device__ __forceinline__ void mma16(float* c, const uint32_t* a, const uint32_t* b){
    asm volatile("mma.sync.aligned.m16n8k16.row.col.f32.f16.f16.f32 "
      "{%0,%1,%2,%3},{%4,%5,%6,%7},{%8,%9},{%0,%1,%2,%3};"
      : "+f"(c[0]),"+f"(c[1]),"+f"(c[2]),"+f"(c[3])
      : "r"(a[0]),"r"(a[1]),"r"(a[2]),"r"(a[3]),"r"(b[0]),"r"(b[1]));
}
// store 8 contiguous fp32 -> 8 fp16 at dst (16B)
__device__ __forceinline__ void store8h(__half* dst, const float* __restrict__ src){
    float4 v0 = *(const float4*)src;
    float4 v1 = *(const float4*)(src + 4);
    __half2 h[4];
    h[0] = __float22half2_rn(make_float2(v0.x, v0.y));
    h[1] = __float22half2_rn(make_float2(v0.z, v0.w));
    h[2] = __float22half2_rn(make_float2(v1.x, v1.y));
    h[3] = __float22half2_rn(make_float2(v1.z, v1.w));
    *(uint4*)dst = *(uint4*)h;
}
__device__ __forceinline__ void store8z(__half* dst){
    *(uint4*)dst = make_uint4(0u, 0u, 0u, 0u);
}
// MLP=4 batched fp32->fp16 grid-stride conversion: n4 in float4 units (divisible by 4)
__device__ __forceinline__ void conv_mlp4(const float* __restrict__ src, __half* dst,
                                          size_t n4, size_t wi, size_t nw){
    const float4* s4 = (const float4*)src;
    __half2* o = (__half2*)dst;
    for (size_t b = wi*4; b < n4; b += nw*4){
        float4 v[4];
        #pragma unroll
        for (int u = 0; u < 4; u++) v[u] = s4[b + u];
        #pragma unroll
        for (int u = 0; u < 4; u++){
            __half2 h[2];
            h[0] = __float22half2_rn(make_float2(v[u].x, v[u].y));
            h[1] = __float22half2_rn(make_float2(v[u].z, v[u].w));
            o[2*(b + u)]     = h[0];
            o[2*(b + u) + 1] = h[1];
        }
    }
}

// ---------------- BN=128 mainloop compute ----------------
__device__ __forceinline__ void stage_mma(uint32_t smA, uint32_t smB,
                                          int lane, int wm, int wn,
                                          float (*acc)[4][4])
{
    int ra = (lane & 7) + (((lane >> 3) & 1) << 3);
    int ka = lane >> 4;
    int rb = (lane & 7) + ((lane >> 4) << 3);
    int kb = (lane >> 3) & 1;
    #pragma unroll
    for (int ks = 0; ks < 4; ks++){
        uint32_t a[4][4], b[2][4];
        #pragma unroll
        for (int mf = 0; mf < 4; mf++){
            int row = wm*64 + mf*16 + ra;
            int kgr = ks*2 + ka;
            ldsm4(a[mf], smA + row*128 + ((kgr ^ (row & 7)) << 4));
        }
        #pragma unroll
        for (int nfp = 0; nfp < 2; nfp++){
            int row = wn*32 + nfp*16 + rb;
            int kgr = ks*2 + kb;
            ldsm4(b[nfp], smB + row*128 + ((kgr ^ (row & 7)) << 4));
        }
        #pragma unroll
        for (int mf = 0; mf < 4; mf++){
            mma16(acc[mf][0], a[mf], b[0] + 0);
            mma16(acc[mf][1], a[mf], b[0] + 2);
            mma16(acc[mf][2], a[mf], b[1] + 0);
            mma16(acc[mf][3], a[mf], b[1] + 2);
        }
    }
}

// ---------------- BN=64 mainloop compute (lora-A GEMM) ----------------
__device__ __forceinline__ void stage_mma64(uint32_t smA, uint32_t smB,
                                            int lane, int wm, int wn,
                                            float (*acc)[4][4])   // acc[2][4][4]
{
    int ra = (lane & 7) + (((lane >> 3) & 1) << 3);
    int ka = lane >> 4;
    int rb = (lane & 7) + ((lane >> 4) << 3);
    int kb = (lane >> 3) & 1;
    #pragma unroll
    for (int ks = 0; ks < 4; ks++){
        uint32_t a[2][4], b[2][4];
        #pragma unroll
        for (int mf = 0; mf < 2; mf++){
            int row = wm*32 + mf*16 + ra;
            int kgr = ks*2 + ka;
            ldsm4(a[mf], smA + row*128 + ((kgr ^ (row & 7)) << 4));
        }
        #pragma unroll
        for (int nfp = 0; nfp < 2; nfp++){
            int row = wn*32 + nfp*16 + rb;
            int kgr = ks*2 + kb;
            ldsm4(b[nfp], smB + row*128 + ((kgr ^ (row & 7)) << 4));
        }
        #pragma unroll
        for (int mf = 0; mf < 2; mf++){
            mma16(acc[mf][0], a[mf], b[0] + 0);
            mma16(acc[mf][1], a[mf], b[0] + 2);
            mma16(acc[mf][2], a[mf], b[1] + 0);
            mma16(acc[mf][3], a[mf], b[1] + 2);
        }
    }
}

// ---------------- setup ----------------
__global__ void k_setup(const int* __restrict__ topk_ids, const float* __restrict__ topk_w,
                        const int* __restrict__ widx, const int* __restrict__ seq_lens,
                        const float* __restrict__ scalings)
{
    __shared__ int cnt[NEXP*NADP], off[NEXP*NADP], cur[NEXP*NADP], cum[NSEQ];
    int tid = threadIdx.x;
    if (tid < NEXP*NADP) cnt[tid] = 0;
    __syncthreads();
    if (tid == 0){ int c = 0; for (int s = 0; s < NSEQ; s++){ c += seq_lens[s]; cum[s] = c; } }
    __syncthreads();
    for (int p = tid; p < NPAIR; p += blockDim.x){
        int n = p / TOPK; int e = topk_ids[p];
        int s = 0; while (n >= cum[s]) s++;
        atomicAdd(&cnt[e*NADP + widx[s]], 1);
    }
    __syncthreads();
    if (tid == 0){
        int acc = 0;
        for (int k = 0; k < NEXP*NADP; k++){ off[k] = acc; cur[k] = acc; acc += cnt[k]; }
        int nt = 0;
        for (int e = 0; e < NEXP; e++){
            int base = off[e*NADP];
            int c = cnt[e*NADP] + cnt[e*NADP+1];
            for (int r0 = 0; r0 < c; r0 += BM){
                g2_e[nt] = e; g2_m0[nt] = base + r0; g2_rows[nt] = min(BM, c - r0); nt++;
            }
        }
        g2_ntiles = nt;
    }
    __syncthreads();
    for (int p = tid; p < NPAIR; p += blockDim.x){
        int n = p / TOPK; int e = topk_ids[p];
        int s = 0; while (n >= cum[s]) s++;
        int a = widx[s];
        int slot = atomicAdd(&cur[e*NADP + a], 1);
        g_tok[slot] = n; g_w[slot] = topk_w[p]; g_ad[slot] = a;
        g_scale[slot] = scalings[a];
    }
}

// ---------------- prep: lora tiles (vectorized) + gather + zero ----------------
__global__ void k_preall(const float* __restrict__ x,
                         const float* __restrict__ gate_a, const float* __restrict__ up_a,
                         const float* __restrict__ down_a,
                         const float* __restrict__ gb, const float* __restrict__ ub,
                         const float* __restrict__ db, const int* __restrict__ ranks,
                         float* __restrict__ out)
{
    size_t stride = (size_t)gridDim.x*blockDim.x;
    size_t tid0 = (size_t)blockIdx.x*blockDim.x + threadIdx.x;
    int r0 = ranks[0], r1 = ranks[1];
    // gather x rows to fp16 by slot
    {
        const size_t n = (size_t)NPAIR*(HID/4);
        for (size_t i = tid0; i < n; i += stride){
            int slot = (int)(i >> 8);
            int c = (int)(i & 255);
            float4 v = ((const float4*)(x + (size_t)g_tok[slot]*HID))[c];
            __half2* xh = (__half2*)(g_xg_h + (size_t)slot*HID);
            xh[2*c]   = __float22half2_rn(make_float2(v.x, v.y));
            xh[2*c+1] = __float22half2_rn(make_float2(v.z, v.w));
        }
    }
    // zero out + zd_f
    {
        const size_t n = (size_t)NTOK*HID/4;
        for (size_t i = tid0; i < n; i += stride)
            ((float4*)out)[i] = make_float4(0.f, 0.f, 0.f, 0.f);
        const size_t nz = (size_t)NPAIR*32/4;
        for (size_t i = tid0; i < nz; i += stride)
            ((float4*)g_zd_f)[i] = make_float4(0.f, 0.f, 0.f, 0.f);
    }
    // bg_ext: rows = NEXP*2*ITR, 8 blocks of 8 halfs per row
    {
        const size_t n1 = (size_t)NEXP*2*ITR*8;
        for (size_t i = tid0; i < n1; i += stride){
            int blk = (int)(i & 7);
            size_t R = i >> 3;
            int e = (int)(R / (2*ITR));
            int r = (int)(R % (2*ITR));
            int j = r >> 1;
            __half* dst = g_bg_ext + R*64 + blk*8;
            int c0 = blk*8;
            const float* src = 0;
            if (!(r & 1)){
                if (c0 < 16)                 src = gb + ((size_t)(0*NEXP + e)*ITR + j)*RNK + c0;
                else if (c0 >= 32 && c0 < 48) src = gb + ((size_t)(1*NEXP + e)*ITR + j)*RNK + (c0 - 32);
            } else {
                if (c0 >= 16 && c0 < 32)     src = ub + ((size_t)(0*NEXP + e)*ITR + j)*RNK + (c0 - 16);
                else if (c0 >= 48)           src = ub + ((size_t)(1*NEXP + e)*ITR + j)*RNK + (c0 - 48);
            }
            if (src) store8h(dst, src); else store8z(dst);
        }
    }
    // bd_ext: rows = NEXP*HID
    {
        const size_t n2 = (size_t)NEXP*HID*8;
        for (size_t i = tid0; i < n2; i += stride){
            int blk = (int)(i & 7);
            size_t R = i >> 3;
            int e = (int)(R >> 10);
            int h = (int)(R & (HID-1));
            __half* dst = g_bd_ext + R*64 + blk*8;
            int c0 = blk*8;
            const float* src = 0;
            if (c0 < 16)      src = db + ((size_t)(0*NEXP + e)*HID + h)*RNK + c0;
            else if (c0 < 32) src = db + ((size_t)(1*NEXP + e)*HID + h)*RNK + (c0 - 16);
            if (src) store8h(dst, src); else store8z(dst);
        }
    }
    // a1h: rows = NEXP*64, HID cols -> HID/8 blocks per row
    {
        const size_t n3 = (size_t)NEXP*64*(HID/8);
        for (size_t i = tid0; i < n3; i += stride){
            int blk = (int)(i & (HID/8 - 1));
            size_t R = i >> 7;
            int e = (int)(R >> 6);
            int r = (int)(R & 63);
            int aidx = r >> 5, type = (r >> 4) & 1, rr = r & 15;
            int rk = aidx ? r1 : r0;
            __half* dst = g_a1h + R*HID + blk*8;
            if (rr < rk){
                const float* src = (type == 0 ? gate_a : up_a)
                    + ((size_t)((aidx*NEXP + e)*RNK) + rr)*HID + blk*8;
                store8h(dst, src);
            } else store8z(dst);
        }
    }
    // a2h: rows = NEXP*64, ITR cols -> ITR/8 blocks per row
    {
        const size_t n4 = (size_t)NEXP*64*(ITR/8);
        for (size_t i = tid0; i < n4; i += stride){
            int blk = (int)(i % (ITR/8));
            size_t R = i / (ITR/8);
            int e = (int)(R >> 6);
            int r = (int)(R & 63);
            __half* dst = g_a2h + R*ITR + blk*8;
            bool live = false;
            const float* src = 0;
            if (r < 32){
                int aidx = r >> 4, rr = r & 15;
                int rk = aidx ? r1 : r0;
                if (rr < rk){
                    live = true;
                    src = down_a + ((size_t)((aidx*NEXP + e)*RNK) + rr)*ITR + blk*8;
                }
            }
            if (live) store8h(dst, src); else store8z(dst);
        }
    }
}

// ---------------- lora-A GEMM fill ----------------
__device__ __forceinline__ void fillL(uint32_t smb, int s, int kc, int tid,
                                      const __half* Ab, int lda, const __half* Bb)
{
    uint32_t ab = smb + s*LSTAGE;
    uint32_t bb = ab + 16384;
    #pragma unroll
    for (int q = 0; q < 4; q++){
        int G = tid + 256*q; int row = G >> 3, gr = G & 7;
        cpa16(ab + row*128 + ((gr ^ (row & 7)) << 4), Ab + (size_t)row*lda + kc*64 + gr*8);
    }
    #pragma unroll
    for (int q = 0; q < 2; q++){
        int G = tid + 256*q; int row = G >> 3, gr = G & 7;
        cpa16(bb + row*128 + ((gr ^ (row & 7)) << 4), Bb + (size_t)row*lda + kc*64 + gr*8);
    }
}

// ---------------- lora-A GEMM for zgu; extra blocks convert Wgu (MLP=4) ----------------
__global__ __launch_bounds__(256, 2) void k_loraA(const float* __restrict__ wgu)
{
    int t = blockIdx.x;
    if (t >= MAXT){
        size_t wi = (size_t)(t - MAXT)*blockDim.x + threadIdx.x;
        size_t nw = (size_t)(gridDim.x - MAXT)*blockDim.x;
        conv_mlp4(wgu, g_wgu_h, (size_t)NEXP*2*ITR*HID/4, wi, nw);
        return;
    }
    if (t >= g2_ntiles) return;
    int e = g2_e[t], m0 = g2_m0[t], rows = g2_rows[t];

    const __half* Ab = g_xg_h + (size_t)m0*HID;
    const __half* Bb = g_a1h + (size_t)e*64*HID;
    const int lda = HID, nk = 16;

    extern __shared__ char smc[];
    uint32_t smb = s2u(smc);
    int tid = threadIdx.x, lane = tid & 31, wid = tid >> 5;
    int wm = wid & 3, wn = wid >> 2;

    float acc[2][4][4];
    #pragma unroll
    for (int i = 0; i < 2; i++)
        #pragma unroll
        for (int j = 0; j < 4; j++)
            #pragma unroll
            for (int k = 0; k < 4; k++) acc[i][j][k] = 0.f;

    fillL(smb, 0, 0, tid, Ab, lda, Bb); cp_commit();
    fillL(smb, 1, 1, tid, Ab, lda, Bb); cp_commit();
    int sC = 0, sF = 2;
    for (int kc = 0; kc < nk; kc++){
        cp_wait1();
        __syncthreads();
        if (kc + 2 < nk){ fillL(smb, sF, kc + 2, tid, Ab, lda, Bb); }
        cp_commit();
        uint32_t st = smb + sC*LSTAGE;
        stage_mma64(st, st + 16384, lane, wm, wn, acc);
        sC = (sC == 2) ? 0 : sC + 1;
        sF = (sF == 2) ? 0 : sF + 1;
    }

    int g = lane >> 2, tg = lane & 3;
    #pragma unroll
    for (int mf = 0; mf < 2; mf++){
        #pragma unroll
        for (int h = 0; h < 2; h++){
            int row = wm*32 + mf*16 + g + h*8;
            if (row >= rows) continue;
            int slot = m0 + row;
            int a = g_ad[slot];
            float sc = g_scale[slot];
            __half* orow = g_zgu_h + (size_t)slot*64;
            #pragma unroll
            for (int nf = 0; nf < 4; nf++){
                #pragma unroll
                for (int p = 0; p < 2; p++){
                    int c = wn*32 + nf*8 + 2*tg + p;
                    float v = acc[mf][nf][h*2 + p];
                    bool keep = (a == 0) ? (c < 32) : (c >= 32);
                    orow[c] = __float2half(keep ? sc*v : 0.f);
                }
            }
        }
    }
}

// ---------------- GEMM1 fill ----------------
__device__ __forceinline__ void fill1(uint32_t smb, int s, int kc, int tid,
                                      int e, int m0, int j064)
{
    uint32_t ab = smb + s*STAGEB;
    uint32_t bb = ab + 16384;
    #pragma unroll
    for (int q = 0; q < 4; q++){
        int G = tid + 256*q; int row = G >> 3, gr = G & 7;
        uint32_t off = row*128 + ((gr ^ (row & 7)) << 4);
        const __half* sa = (kc < 16)
            ? g_xg_h + (size_t)(m0 + row)*HID + kc*64 + gr*8
            : g_zgu_h + (size_t)(m0 + row)*64 + gr*8;
        cpa16(ab + off, sa);
        const __half* sb;
        if (kc < 16){
            int sr = ((row & 1) ? ITR : 0) + j064 + (row >> 1);
            sb = g_wgu_h + ((size_t)e*(2*ITR) + sr)*HID + kc*64 + gr*8;
        } else {
            sb = g_bg_ext + ((size_t)e*(2*ITR) + 2*j064 + row)*64 + gr*8;
        }
        cpa16(bb + off, sb);
    }
}

// ---------------- GEMM1: gate/up + LoRA + SiLU -> act; zd partials; extra y convert Wd ----------------
__global__ __launch_bounds__(256, 2) void k_gemm1(const float* __restrict__ wd)
{
    int t = blockIdx.x;
    if (blockIdx.y >= NCT1){
        size_t wi = ((size_t)(blockIdx.y - NCT1)*MAXT + t)*blockDim.x + threadIdx.x;
        size_t nw = (size_t)NEY*MAXT*blockDim.x;
        conv_mlp4(wd, g_wd_h, (size_t)NEXP*HID*ITR/4, wi, nw);
        return;
    }
    if (t >= g2_ntiles) return;
    int e = g2_e[t], m0 = g2_m0[t], rows = g2_rows[t];
    int j064 = blockIdx.y * 64;

    extern __shared__ char smc[];
    uint32_t smb = s2u(smc);
    int tid = threadIdx.x, lane = tid & 31, wid = tid >> 5;
    int wm = wid & 1, wn = wid >> 1;

    float acc[4][4][4];
    #pragma unroll
    for (int i = 0; i < 4; i++)
        #pragma unroll
        for (int j = 0; j < 4; j++)
            #pragma unroll
            for (int k = 0; k < 4; k++) acc[i][j][k] = 0.f;

    fill1(smb, 0, 0, tid, e, m0, j064); cp_commit();
    fill1(smb, 1, 1, tid, e, m0, j064); cp_commit();
    int sC = 0, sF = 2;
    for (int kc = 0; kc < NK1; kc++){
        cp_wait1();
        __syncthreads();
        if (kc + 2 < NK1){ fill1(smb, sF, kc + 2, tid, e, m0, j064); }
        cp_commit();
        uint32_t st = smb + sC*STAGEB;
        stage_mma(st, st + 16384, lane, wm, wn, acc);
        sC = (sC == 2) ? 0 : sC + 1;
        sF = (sF == 2) ? 0 : sF + 1;
    }

    // fetch da tile for zd partial GEMM: rows 0..31 of g_a2h[e], K slice j064..j064+63
    {
        int row = tid >> 3, gr = tid & 7;  // 32 rows x 8 granules = 256
        cpa16(smb + 16384 + row*128 + ((gr ^ (row & 7)) << 4),
              g_a2h + ((size_t)e*64 + row)*ITR + j064 + gr*8);
        cp_commit();
    }

    int g = lane >> 2, tg = lane & 3;
    #pragma unroll
    for (int mf = 0; mf < 4; mf++){
        #pragma unroll
        for (int h = 0; h < 2; h++){
            int row = wm*64 + mf*16 + g + h*8;
            if (row >= rows) continue;
            __half* arow = g_act_h + (size_t)(m0 + row)*ITR + j064;
            #pragma unroll
            for (int nf = 0; nf < 4; nf++){
                float gate = acc[mf][nf][h*2 + 0];
                float up   = acc[mf][nf][h*2 + 1];
                float act = gate / (1.f + __expf(-gate)) * up;
                __half ah = __float2half(act);
                int c = wn*16 + nf*4 + tg;
                arow[c] = ah;
                *(__half*)(smc + row*128 + (((c >> 3) ^ (row & 7)) << 4) + (c & 7)*2) = ah;
            }
        }
    }
    cp_wait0();
    __syncthreads();

    // zd partial: C[128x32] = act_sm[128x64] @ da_sm[32x64]^T, atomically into g_zd_f
    {
        int wm2 = wid >> 1, wn2 = wid & 1;
        float zacc[2][2][4];
        #pragma unroll
        for (int i = 0; i < 2; i++)
            #pragma unroll
            for (int j = 0; j < 2; j++)
                #pragma unroll
                for (int k = 0; k < 4; k++) zacc[i][j][k] = 0.f;
        int ra = (lane & 7) + (((lane >> 3) & 1) << 3);
        int ka = lane >> 4;
        int rb = (lane & 7) + ((lane >> 4) << 3);
        int kb = (lane >> 3) & 1;
        #pragma unroll
        for (int ks = 0; ks < 4; ks++){
            uint32_t a[2][4], b4[4];
            #pragma unroll
            for (int mf = 0; mf < 2; mf++){
                int row = wm2*32 + mf*16 + ra;
                int kgr = ks*2 + ka;
                ldsm4(a[mf], smb + row*128 + ((kgr ^ (row & 7)) << 4));
            }
            {
                int row = wn2*16 + rb;
                int kgr = ks*2 + kb;
                ldsm4(b4, smb + 16384 + row*128 + ((kgr ^ (row & 7)) << 4));
            }
            #pragma unroll
            for (int mf = 0; mf < 2; mf++){
                mma16(zacc[mf][0], a[mf], b4 + 0);
                mma16(zacc[mf][1], a[mf], b4 + 2);
            }
        }
        #pragma unroll
        for (int mf = 0; mf < 2; mf++){
            #pragma unroll
            for (int h = 0; h < 2; h++){
                int row = wm2*32 + mf*16 + g + h*8;
                if (row >= rows) continue;
                float* zr = g_zd_f + (size_t)(m0 + row)*32;
                #pragma unroll
                for (int nf = 0; nf < 2; nf++){
                    int c = wn2*16 + nf*8 + 2*tg;
                    atomicAdd(zr + c,     zacc[mf][nf][h*2 + 0]);
                    atomicAdd(zr + c + 1, zacc[mf][nf][h*2 + 1]);
                }
            }
        }
    }
}

// ---------------- zd convert: adapter select + scale -> fp16 ----------------
__global__ void k_zdconv()
{
    int idx = blockIdx.x*blockDim.x + threadIdx.x;   // NPAIR*64 total
    int slot = idx >> 6;
    int c = idx & 63;
    if (slot >= NPAIR) return;
    int a = g_ad[slot];
    float sc = g_scale[slot];
    float v = 0.f;
    if (c < 16){ if (a == 0) v = sc * g_zd_f[(size_t)slot*32 + c]; }
    else if (c < 32){ if (a == 1) v = sc * g_zd_f[(size_t)slot*32 + c]; }
    g_zd_h[(size_t)slot*64 + c] = __float2half(v);
}

// ---------------- GEMM2 fill ----------------
__device__ __forceinline__ void fill2(uint32_t smb, int s, int kc, int tid,
                                      int e, int m0, int j0)
{
    uint32_t ab = smb + s*STAGEB;
    uint32_t bb = ab + 16384;
    #pragma unroll
    for (int q = 0; q < 4; q++){
        int G = tid + 256*q; int row = G >> 3, gr = G & 7;
        uint32_t off = row*128 + ((gr ^ (row & 7)) << 4);
        const __half* sa = (kc < 44)
            ? g_act_h + (size_t)(m0 + row)*ITR + kc*64 + gr*8
            : g_zd_h + (size_t)(m0 + row)*64 + gr*8;
        cpa16(ab + off, sa);
        const __half* sb = (kc < 44)
            ? g_wd_h + ((size_t)e*HID + j0 + row)*ITR + kc*64 + gr*8
            : g_bd_ext + ((size_t)e*HID + j0 + row)*64 + gr*8;
        cpa16(bb + off, sb);
    }
}

// ---------------- GEMM2: down proj + LoRA, weighted, atomic into out ----------------
__global__ __launch_bounds__(256, 2) void k_gemm2(float* __restrict__ out)
{
    int t = blockIdx.x;
    if (t >= g2_ntiles) return;
    int e = g2_e[t], m0 = g2_m0[t], rows = g2_rows[t];
    int j0 = blockIdx.y * BN;

    extern __shared__ char smc[];
    uint32_t smb = s2u(smc);
    __shared__ float s_wt[BM];
    __shared__ int   s_tok[BM];
    int tid = threadIdx.x, lane = tid & 31, wid = tid >> 5;
    int wm = wid & 1, wn = wid >> 1;
    if (tid < BM){
        int s = min(m0 + tid, NPAIR - 1);
        s_wt[tid] = g_w[s]; s_tok[tid] = g_tok[s];
    }

    float acc[4][4][4];
    #pragma unroll
    for (int i = 0; i < 4; i++)
        #pragma unroll
        for (int j = 0; j < 4; j++)
            #pragma unroll
            for (int k = 0; k < 4; k++) acc[i][j][k] = 0.f;

    fill2(smb, 0, 0, tid, e, m0, j0); cp_commit();
    fill2(smb, 1, 1, tid, e, m0, j0); cp_commit();
    int sC = 0, sF = 2;
    for (int kc = 0; kc < NK2; kc++){
        cp_wait1();
        __syncthreads();
        if (kc + 2 < NK2){ fill2(smb, sF, kc + 2, tid, e, m0, j0); }
        cp_commit();
        uint32_t st = smb + sC*STAGEB;
        stage_mma(st, st + 16384, lane, wm, wn, acc);
        sC = (sC == 2) ? 0 : sC + 1;
        sF = (sF == 2) ? 0 : sF + 1;
    }

    int g = lane >> 2, tg = lane & 3;
    #pragma unroll
    for (int mf = 0; mf < 4; mf++){
        #pragma unroll
        for (int h = 0; h < 2; h++){
            int row = wm*64 + mf*16 + g + h*8;
            if (row >= rows) continue;
            float w = s_wt[row];
            float* orow = out + (size_t)s_tok[row]*HID + j0;
            #pragma unroll
            for (int nf = 0; nf < 4; nf++){
                int c = wn*32 + nf*8 + 2*tg;
                atomicAdd(orow + c,     w * acc[mf][nf][h*2 + 0]);
                atomicAdd(orow + c + 1, w * acc[mf][nf][h*2 + 1]);
            }
        }
    }
}

// ---------------- launch ----------------
extern "C" void kernel_launch(void* const* d_in, const int* in_sizes, int n_in,
                              void* d_out, int out_size)
{
    const float* x        = (const float*)d_in[0];
    const int*   topk_ids = (const int*)  d_in[1];
    const float* topk_w   = (const float*)d_in[2];
    const float* gate_a   = (const float*)d_in[3];
    const float* gate_b   = (const float*)d_in[4];
    const float* up_a     = (const float*)d_in[5];
    const float* up_b     = (const float*)d_in[6];
    const float* down_a   = (const float*)d_in[7];
    const float* down_b   = (const float*)d_in[8];
    const int*   widx     = (const int*)  d_in[9];
    const int*   seq_lens = (const int*)  d_in[10];
    const int*   ranks    = (const int*)  d_in[11];
    const float* scalings = (const float*)d_in[12];
    const float* Wgu      = (const float*)d_in[13];
    const float* Wd       = (const float*)d_in[14];
    float* out = (float*)d_out;

    static int s_attr_done = 0;
    if (!s_attr_done){
        cudaFuncSetAttribute(k_gemm1, cudaFuncAttributeMaxDynamicSharedMemorySize, SMEM_DYN);
        cudaFuncSetAttribute(k_gemm2, cudaFuncAttributeMaxDynamicSharedMemorySize, SMEM_DYN);
        cudaFuncSetAttribute(k_loraA, cudaFuncAttributeMaxDynamicSharedMemorySize, LSMEM);
        s_attr_done = 1;
    }

    k_setup<<<1, 256>>>(topk_ids, topk_w, widx, seq_lens, scalings);
    k_preall<<<2048, 256>>>(x, gate_a, up_a, down_a,
                            gate_b, up_b, down_b, ranks, out);
    k_loraA<<<MAXT + NCV1, 256, LSMEM>>>(Wgu);
    k_gemm1<<<dim3(MAXT, NCT1 + NEY), 256, SMEM_DYN>>>(Wd);
    k_zdconv<<<NPAIR*64/256, 256>>>();
    k_gemm2<<<dim3(MAXT, NCT2), 256, SMEM_DYN>>>(out);
}